// round 12
// baseline (speedup 1.0000x reference)
#include <cuda_runtime.h>
#include <cuda_bf16.h>
#include <cuda_fp16.h>
#include <cstdint>
#include <cstddef>

// DSAttention: preprocessed operands; QK = 3-term bf16 hi/lo split mma.sync,
// PV = single-term fp16. 32 rows per warp (BM=128, 4 warps): each K/V smem
// fragment load feeds two 16-row MMA blocks -> crossbar bytes per FLOP halved.

#define LOG2E_SCALE 0.18033688011112042f   // (1/8)*log2(e)
#define PMAX (4 * 8 * 2048 * 64)           // B*H*L*E
#define DMAX (4 * 2048)                    // B*L

__device__ __nv_bfloat16 g_Qh[PMAX], g_Ql[PMAX];
__device__ __nv_bfloat16 g_Kh[PMAX], g_Kl[PMAX];
__device__ __half        g_Vh[PMAX];
__device__ float         g_delta[DMAX];

#define NTHREADS 128
#define BM 128
#define BN 64

#define O_KH 0
#define O_KL 8192
#define O_VH 16384
#define O_BETA 24576
#define STAGE_BYTES 24832
#define SM_TOTAL (2 * STAGE_BYTES)

#define SW(row, byte) (((row) * 128) + ((byte) ^ (((row) & 7) << 4)))

#define CP_ASYNC16(dst, src) \
    asm volatile("cp.async.cg.shared.global [%0], [%1], 16;" :: "r"(dst), "l"(src))
#define CP_COMMIT asm volatile("cp.async.commit_group;" ::: "memory")
#define CP_WAIT0  asm volatile("cp.async.wait_group 0;" ::: "memory")

__device__ __forceinline__ void mma_bf16(float c[4], uint32_t a0, uint32_t a1,
                                         uint32_t a2, uint32_t a3,
                                         uint32_t b0, uint32_t b1) {
    asm volatile(
        "mma.sync.aligned.m16n8k16.row.col.f32.bf16.bf16.f32 "
        "{%0,%1,%2,%3}, {%4,%5,%6,%7}, {%8,%9}, {%0,%1,%2,%3};"
        : "+f"(c[0]), "+f"(c[1]), "+f"(c[2]), "+f"(c[3])
        : "r"(a0), "r"(a1), "r"(a2), "r"(a3), "r"(b0), "r"(b1));
}
__device__ __forceinline__ void mma_f16(float c[4], uint32_t a0, uint32_t a1,
                                        uint32_t a2, uint32_t a3,
                                        uint32_t b0, uint32_t b1) {
    asm volatile(
        "mma.sync.aligned.m16n8k16.row.col.f32.f16.f16.f32 "
        "{%0,%1,%2,%3}, {%4,%5,%6,%7}, {%8,%9}, {%0,%1,%2,%3};"
        : "+f"(c[0]), "+f"(c[1]), "+f"(c[2]), "+f"(c[3])
        : "r"(a0), "r"(a1), "r"(a2), "r"(a3), "r"(b0), "r"(b1));
}
#define LDSM_X4(r, a) \
    asm volatile("ldmatrix.sync.aligned.m8n8.x4.shared.b16 {%0,%1,%2,%3}, [%4];" \
        : "=r"((r)[0]), "=r"((r)[1]), "=r"((r)[2]), "=r"((r)[3]) : "r"(a))
#define LDSM_X4_T(r, a) \
    asm volatile("ldmatrix.sync.aligned.m8n8.x4.trans.shared.b16 {%0,%1,%2,%3}, [%4];" \
        : "=r"((r)[0]), "=r"((r)[1]), "=r"((r)[2]), "=r"((r)[3]) : "r"(a))

__device__ __forceinline__ uint32_t smem_to_u32(const void* p) {
    uint32_t a;
    asm("{ .reg .u64 t; cvta.to.shared.u64 t, %1; cvt.u32.u64 %0, t; }" : "=r"(a) : "l"(p));
    return a;
}
__device__ __forceinline__ float ex2(float x) {
    float r; asm("ex2.approx.ftz.f32 %0, %1;" : "=f"(r) : "f"(x)); return r;
}
__device__ __forceinline__ uint32_t packf16(float lo, float hi) {
    uint32_t r; asm("cvt.rn.f16x2.f32 %0, %1, %2;" : "=r"(r) : "f"(hi), "f"(lo)); return r;
}
__device__ __forceinline__ uint32_t h2ex2(uint32_t x) {
    uint32_t r; asm("ex2.approx.f16x2 %0, %1;" : "=r"(r) : "r"(x)); return r;
}
__device__ __forceinline__ uint32_t hmax2(uint32_t a, uint32_t b) {
    uint32_t r; asm("max.f16x2 %0, %1, %2;" : "=r"(r) : "r"(a), "r"(b)); return r;
}
__device__ __forceinline__ void split_pack(float a, float b, uint32_t& hi, uint32_t& lo) {
    __nv_bfloat16 ha = __float2bfloat16(a);
    __nv_bfloat16 hb = __float2bfloat16(b);
    __nv_bfloat16 la = __float2bfloat16(a - __bfloat162float(ha));
    __nv_bfloat16 lb = __float2bfloat16(b - __bfloat162float(hb));
    hi = ((uint32_t)__bfloat16_as_ushort(hb) << 16) | (uint32_t)__bfloat16_as_ushort(ha);
    lo = ((uint32_t)__bfloat16_as_ushort(lb) << 16) | (uint32_t)__bfloat16_as_ushort(la);
}

// ---------------- preprocessing ----------------
__global__ void prep_kernel(const float* __restrict__ Q, const float* __restrict__ K,
                            const float* __restrict__ V, const float* __restrict__ tau,
                            const float* __restrict__ delta, int B, int L, int H)
{
    const int idx = blockIdx.x * blockDim.x + threadIdx.x;
    const int total = B * L * H * 16;
    if (idx < B * L) g_delta[idx] = delta[idx] * LOG2E_SCALE;
    if (idx >= total) return;
    const int e4 = (idx & 15) << 2;
    int t = idx >> 4;
    const int h = t % H; t /= H;
    const int l = t % L;
    const int b = t / L;

    const size_t in_ofs  = ((size_t)((b * L + l) * H + h)) * 64 + e4;
    const size_t out_ofs = ((size_t)((b * H + h) * L + l)) * 64 + e4;

    const float qs = tau[b] * LOG2E_SCALE;
    uint32_t h0, l0, h1, l1;

    const float4 q = *(const float4*)(Q + in_ofs);
    split_pack(q.x * qs, q.y * qs, h0, l0);
    split_pack(q.z * qs, q.w * qs, h1, l1);
    *(uint2*)(g_Qh + out_ofs) = make_uint2(h0, h1);
    *(uint2*)(g_Ql + out_ofs) = make_uint2(l0, l1);

    const float4 k = *(const float4*)(K + in_ofs);
    split_pack(k.x, k.y, h0, l0);
    split_pack(k.z, k.w, h1, l1);
    *(uint2*)(g_Kh + out_ofs) = make_uint2(h0, h1);
    *(uint2*)(g_Kl + out_ofs) = make_uint2(l0, l1);

    const float4 v = *(const float4*)(V + in_ofs);
    *(uint2*)(g_Vh + out_ofs) = make_uint2(packf16(v.x, v.y), packf16(v.z, v.w));
}

// ---------------- stage one KV tile via cp.async ----------------
__device__ __forceinline__ void stage_tile(uint32_t sb,
                                           const __nv_bfloat16* kh, const __nv_bfloat16* kl,
                                           const __half* vh, const float* dl, int tid)
{
#pragma unroll
    for (int i = 0; i < 4; ++i) {
        const int c = tid + NTHREADS * i;
        const int r = c >> 3, s8 = (c & 7) << 3;
        const uint32_t d = SW(r, s8 * 2);
        const size_t go = (size_t)r * 64 + s8;
        CP_ASYNC16(sb + O_KH + d, kh + go);
        CP_ASYNC16(sb + O_KL + d, kl + go);
        CP_ASYNC16(sb + O_VH + d, vh + go);
    }
    if (tid < 16) CP_ASYNC16(sb + O_BETA + tid * 16, dl + tid * 4);
}

__global__ __launch_bounds__(NTHREADS, 2)
void dsattn7_kernel(float* __restrict__ Out, int B, int L, int H)
{
    extern __shared__ char smem[];
    const uint32_t smem_u32 = smem_to_u32(smem);

    const int tid  = threadIdx.x;
    const int wid  = tid >> 5;
    const int lane = tid & 31;
    const int g    = lane >> 2;
    const int t    = lane & 3;

    const uint32_t kb_row = (uint32_t)((lane & 7) | ((lane & 16) >> 1));
    const uint32_t kb_byt = (uint32_t)((lane & 8) << 1);
    const uint32_t vb_row = (uint32_t)(lane & 15);
    const uint32_t vb_byt = (uint32_t)((lane & 16) ? 16 : 0);

    const int qt = (int)(gridDim.x - 1u) - (int)blockIdx.x;  // heavy CTAs first
    const int bh = blockIdx.y;
    const int b  = bh / H;
    const int h  = bh % H;
    const int q0 = qt * BM;

    const size_t hb = (size_t)bh * L * 64;
    // this warp's 32 rows: two 16-row MMA blocks
    const int r0g = q0 + 32 * wid + g;        // block0 rows: r0g, r0g+8
    const int r1g = r0g + 8;
    const int r2g = r0g + 16;                 // block1 rows: r2g, r2g+8
    const int r3g = r0g + 24;

    const __nv_bfloat16* khp = g_Kh + hb;
    const __nv_bfloat16* klp = g_Kl + hb;
    const __half*        vhp = g_Vh + hb;
    const float*         dlp = g_delta + (size_t)b * L;

    stage_tile(smem_u32, khp, klp, vhp, dlp, tid);
    CP_COMMIT;

    // ---- Q A-fragments for both row blocks (already scaled + split) ----
    uint32_t Qh0[4][4], Ql0[4][4], Qh1[4][4], Ql1[4][4];
    {
        const __nv_bfloat16* qh = g_Qh + hb;
        const __nv_bfloat16* ql = g_Ql + hb;
#pragma unroll
        for (int kb = 0; kb < 4; ++kb) {
#pragma unroll
            for (int h2 = 0; h2 < 2; ++h2) {
                const int col = 16 * kb + 2 * t + 8 * h2;
                Qh0[kb][2 * h2 + 0] = *(const uint32_t*)(qh + (size_t)r0g * 64 + col);
                Qh0[kb][2 * h2 + 1] = *(const uint32_t*)(qh + (size_t)r1g * 64 + col);
                Ql0[kb][2 * h2 + 0] = *(const uint32_t*)(ql + (size_t)r0g * 64 + col);
                Ql0[kb][2 * h2 + 1] = *(const uint32_t*)(ql + (size_t)r1g * 64 + col);
                Qh1[kb][2 * h2 + 0] = *(const uint32_t*)(qh + (size_t)r2g * 64 + col);
                Qh1[kb][2 * h2 + 1] = *(const uint32_t*)(qh + (size_t)r3g * 64 + col);
                Ql1[kb][2 * h2 + 0] = *(const uint32_t*)(ql + (size_t)r2g * 64 + col);
                Ql1[kb][2 * h2 + 1] = *(const uint32_t*)(ql + (size_t)r3g * 64 + col);
            }
        }
    }

    float m0 = -1e30f, m1 = -1e30f, m2 = -1e30f, m3 = -1e30f;
    float lacc0[4] = {0.f, 0.f, 0.f, 0.f};
    float lacc1[4] = {0.f, 0.f, 0.f, 0.f};
    float O0[8][4], O1[8][4];
#pragma unroll
    for (int j = 0; j < 8; ++j)
#pragma unroll
        for (int i = 0; i < 4; ++i) { O0[j][i] = 0.0f; O1[j][i] = 0.0f; }

    const uint32_t ONES = 0x3C003C00u;  // fp16 (1.0, 1.0)

    const int nkv = 2 * qt + 2;
    for (int nt = 0; nt < nkv; ++nt) {
        const int cur = nt & 1;
        const uint32_t bufc = smem_u32 + (uint32_t)cur * STAGE_BYTES;

        CP_WAIT0;
        __syncthreads();

        if (nt + 1 < nkv) {
            const int n1 = (nt + 1) * BN;
            stage_tile(smem_u32 + (uint32_t)(cur ^ 1) * STAGE_BYTES,
                       khp + (size_t)n1 * 64, klp + (size_t)n1 * 64,
                       vhp + (size_t)n1 * 64, dlp + n1, tid);
            CP_COMMIT;
        }

        // ---- S = Q.K^T for both row blocks: K frags loaded ONCE ----
        float S0[8][4], S1[8][4];
#pragma unroll
        for (int j = 0; j < 8; ++j)
#pragma unroll
            for (int i = 0; i < 4; ++i) { S0[j][i] = 0.0f; S1[j][i] = 0.0f; }

#pragma unroll
        for (int kb = 0; kb < 4; ++kb) {
#pragma unroll
            for (int njp = 0; njp < 4; ++njp) {
                uint32_t kh[4], kl[4];
                const uint32_t ofs = SW(16u * njp + kb_row, 32u * kb + kb_byt);
                LDSM_X4(kh, bufc + O_KH + ofs);
                LDSM_X4(kl, bufc + O_KL + ofs);
                // row block 0
                mma_bf16(S0[2 * njp],     Qh0[kb][0], Qh0[kb][1], Qh0[kb][2], Qh0[kb][3], kh[0], kh[1]);
                mma_bf16(S0[2 * njp],     Qh0[kb][0], Qh0[kb][1], Qh0[kb][2], Qh0[kb][3], kl[0], kl[1]);
                mma_bf16(S0[2 * njp],     Ql0[kb][0], Ql0[kb][1], Ql0[kb][2], Ql0[kb][3], kh[0], kh[1]);
                mma_bf16(S0[2 * njp + 1], Qh0[kb][0], Qh0[kb][1], Qh0[kb][2], Qh0[kb][3], kh[2], kh[3]);
                mma_bf16(S0[2 * njp + 1], Qh0[kb][0], Qh0[kb][1], Qh0[kb][2], Qh0[kb][3], kl[2], kl[3]);
                mma_bf16(S0[2 * njp + 1], Ql0[kb][0], Ql0[kb][1], Ql0[kb][2], Ql0[kb][3], kh[2], kh[3]);
                // row block 1 (reuses kh/kl)
                mma_bf16(S1[2 * njp],     Qh1[kb][0], Qh1[kb][1], Qh1[kb][2], Qh1[kb][3], kh[0], kh[1]);
                mma_bf16(S1[2 * njp],     Qh1[kb][0], Qh1[kb][1], Qh1[kb][2], Qh1[kb][3], kl[0], kl[1]);
                mma_bf16(S1[2 * njp],     Ql1[kb][0], Ql1[kb][1], Ql1[kb][2], Ql1[kb][3], kh[0], kh[1]);
                mma_bf16(S1[2 * njp + 1], Qh1[kb][0], Qh1[kb][1], Qh1[kb][2], Qh1[kb][3], kh[2], kh[3]);
                mma_bf16(S1[2 * njp + 1], Qh1[kb][0], Qh1[kb][1], Qh1[kb][2], Qh1[kb][3], kl[2], kl[3]);
                mma_bf16(S1[2 * njp + 1], Ql1[kb][0], Ql1[kb][1], Ql1[kb][2], Ql1[kb][3], kh[2], kh[3]);
            }
        }

        // ---- bias (prescaled) + causal mask ----
        const float* beta_c = (const float*)(smem + cur * STAGE_BYTES + O_BETA);
#pragma unroll
        for (int nj = 0; nj < 8; ++nj) {
            const float2 bv = *(const float2*)(beta_c + 8 * nj + 2 * t);
            S0[nj][0] += bv.x; S0[nj][1] += bv.y;
            S0[nj][2] += bv.x; S0[nj][3] += bv.y;
            S1[nj][0] += bv.x; S1[nj][1] += bv.y;
            S1[nj][2] += bv.x; S1[nj][3] += bv.y;
        }
        if (nt + 2 >= nkv) {   // diagonal band spans last two kv tiles
            const int c0b = nt * BN + 2 * t;
#pragma unroll
            for (int nj = 0; nj < 8; ++nj) {
                const int c = c0b + 8 * nj;
                if (c     > r0g) S0[nj][0] = -30000.0f;
                if (c + 1 > r0g) S0[nj][1] = -30000.0f;
                if (c     > r1g) S0[nj][2] = -30000.0f;
                if (c + 1 > r1g) S0[nj][3] = -30000.0f;
                if (c     > r2g) S1[nj][0] = -30000.0f;
                if (c + 1 > r2g) S1[nj][1] = -30000.0f;
                if (c     > r3g) S1[nj][2] = -30000.0f;
                if (c + 1 > r3g) S1[nj][3] = -30000.0f;
            }
        }

        // ---- packed row max (both blocks) ----
        float nm0 = m0, nm1 = m1, nm2 = m2, nm3 = m3;
#pragma unroll
        for (int nj = 0; nj < 8; ++nj) {
            nm0 = fmaxf(nm0, fmaxf(S0[nj][0], S0[nj][1]));
            nm1 = fmaxf(nm1, fmaxf(S0[nj][2], S0[nj][3]));
            nm2 = fmaxf(nm2, fmaxf(S1[nj][0], S1[nj][1]));
            nm3 = fmaxf(nm3, fmaxf(S1[nj][2], S1[nj][3]));
        }
        uint32_t pm0 = packf16(nm0, nm1);
        uint32_t pm1 = packf16(nm2, nm3);
        pm0 = hmax2(pm0, __shfl_xor_sync(0xffffffffu, pm0, 1));
        pm0 = hmax2(pm0, __shfl_xor_sync(0xffffffffu, pm0, 2));
        pm1 = hmax2(pm1, __shfl_xor_sync(0xffffffffu, pm1, 1));
        pm1 = hmax2(pm1, __shfl_xor_sync(0xffffffffu, pm1, 2));
        const __half2 mh0 = *reinterpret_cast<const __half2*>(&pm0);
        const __half2 mh1 = *reinterpret_cast<const __half2*>(&pm1);
        nm0 = __low2float(mh0); nm1 = __high2float(mh0);
        nm2 = __low2float(mh1); nm3 = __high2float(mh1);

        // ---- conditional accumulator rescale ----
        if (!__all_sync(0xffffffffu,
                        (nm0 == m0) & (nm1 == m1) & (nm2 == m2) & (nm3 == m3))) {
            const float c0 = ex2(m0 - nm0);
            const float c1 = ex2(m1 - nm1);
            const float c2 = ex2(m2 - nm2);
            const float c3 = ex2(m3 - nm3);
#pragma unroll
            for (int nj = 0; nj < 8; ++nj) {
                O0[nj][0] *= c0; O0[nj][1] *= c0;
                O0[nj][2] *= c1; O0[nj][3] *= c1;
                O1[nj][0] *= c2; O1[nj][1] *= c2;
                O1[nj][2] *= c3; O1[nj][3] *= c3;
            }
            lacc0[0] *= c0; lacc0[1] *= c0; lacc0[2] *= c1; lacc0[3] *= c1;
            lacc1[0] *= c2; lacc1[1] *= c2; lacc1[2] *= c3; lacc1[3] *= c3;
        }
        m0 = nm0; m1 = nm1; m2 = nm2; m3 = nm3;

        // ---- P = exp2(S - m) in fp16x2 ----
        uint32_t Ph0[8][2], Ph1[8][2];
#pragma unroll
        for (int nj = 0; nj < 8; ++nj) {
            Ph0[nj][0] = h2ex2(packf16(S0[nj][0] - nm0, S0[nj][1] - nm0));
            Ph0[nj][1] = h2ex2(packf16(S0[nj][2] - nm1, S0[nj][3] - nm1));
            Ph1[nj][0] = h2ex2(packf16(S1[nj][0] - nm2, S1[nj][1] - nm2));
            Ph1[nj][1] = h2ex2(packf16(S1[nj][2] - nm3, S1[nj][3] - nm3));
        }

        // ---- O += P.V (both blocks share V frags), l += P.1 ----
#pragma unroll
        for (int jk = 0; jk < 4; ++jk) {
            const uint32_t a0 = Ph0[2 * jk][0], a1 = Ph0[2 * jk][1];
            const uint32_t a2 = Ph0[2 * jk + 1][0], a3 = Ph0[2 * jk + 1][1];
            const uint32_t b0 = Ph1[2 * jk][0], b1 = Ph1[2 * jk][1];
            const uint32_t b2 = Ph1[2 * jk + 1][0], b3 = Ph1[2 * jk + 1][1];
            mma_f16(lacc0, a0, a1, a2, a3, ONES, ONES);
            mma_f16(lacc1, b0, b1, b2, b3, ONES, ONES);
#pragma unroll
            for (int njp = 0; njp < 4; ++njp) {
                uint32_t vh[4];
                const uint32_t ofs = SW(16u * jk + vb_row, 32u * njp + vb_byt);
                LDSM_X4_T(vh, bufc + O_VH + ofs);
                mma_f16(O0[2 * njp],     a0, a1, a2, a3, vh[0], vh[1]);
                mma_f16(O0[2 * njp + 1], a0, a1, a2, a3, vh[2], vh[3]);
                mma_f16(O1[2 * njp],     b0, b1, b2, b3, vh[0], vh[1]);
                mma_f16(O1[2 * njp + 1], b0, b1, b2, b3, vh[2], vh[3]);
            }
        }
        // no end-of-loop sync: next iteration's top sync guards buffer reuse
    }

    // ---- epilogue: 4 rows per thread ----
    const float i0 = 1.0f / lacc0[0];
    const float i1 = 1.0f / lacc0[2];
    const float i2 = 1.0f / lacc1[0];
    const float i3 = 1.0f / lacc1[2];
    float* o0p = Out + ((size_t)((b * L + r0g) * H + h)) * 64;
    float* o1p = Out + ((size_t)((b * L + r1g) * H + h)) * 64;
    float* o2p = Out + ((size_t)((b * L + r2g) * H + h)) * 64;
    float* o3p = Out + ((size_t)((b * L + r3g) * H + h)) * 64;
#pragma unroll
    for (int nj = 0; nj < 8; ++nj) {
        const int d = 8 * nj + 2 * t;
        *(float2*)(o0p + d) = make_float2(O0[nj][0] * i0, O0[nj][1] * i0);
        *(float2*)(o1p + d) = make_float2(O0[nj][2] * i1, O0[nj][3] * i1);
        *(float2*)(o2p + d) = make_float2(O1[nj][0] * i2, O1[nj][1] * i2);
        *(float2*)(o3p + d) = make_float2(O1[nj][2] * i3, O1[nj][3] * i3);
    }
}

extern "C" void kernel_launch(void* const* d_in, const int* in_sizes, int n_in,
                              void* d_out, int out_size)
{
    const float* Q     = (const float*)d_in[0];
    const float* K     = (const float*)d_in[1];
    const float* V     = (const float*)d_in[2];
    const float* tau   = (const float*)d_in[3];
    const float* delta = (const float*)d_in[4];
    float* O = (float*)d_out;

    const int B = in_sizes[3];
    const int L = in_sizes[4] / B;
    const int H = in_sizes[0] / (B * L * 64);

    const int total4 = B * L * H * 16;
    prep_kernel<<<(total4 + 255) / 256, 256>>>(Q, K, V, tau, delta, B, L, H);

    cudaFuncSetAttribute(dsattn7_kernel,
                         cudaFuncAttributeMaxDynamicSharedMemorySize, SM_TOTAL);
    dim3 grid(L / BM, B * H);
    dsattn7_kernel<<<grid, NTHREADS, SM_TOTAL>>>(O, B, L, H);
}

// round 13
// speedup vs baseline: 1.2952x; 1.2952x over previous
#include <cuda_runtime.h>
#include <cuda_bf16.h>
#include <cuda_fp16.h>
#include <cstdint>
#include <cstddef>

// DSAttention: preprocessed operands. QK = 2-term fp16 (Qh·Kh + Qh·Kl, K split
// hi/lo fp16, Q single fp16 -> 64 HMMA/warp-step), PV = single-term fp16.
// cp.async double-buffer, single sync/step, packed f16x2 max, cond rescale.

#define LOG2E_SCALE 0.18033688011112042f   // (1/8)*log2(e)
#define PMAX (4 * 8 * 2048 * 64)           // B*H*L*E
#define DMAX (4 * 2048)                    // B*L

__device__ __half g_Qh[PMAX];
__device__ __half g_Kh[PMAX], g_Kl[PMAX];
__device__ __half g_Vh[PMAX];
__device__ float  g_delta[DMAX];

#define NTHREADS 128
#define BM 64
#define BN 64

#define O_KH 0
#define O_KL 8192
#define O_VH 16384
#define O_BETA 24576
#define STAGE_BYTES 24832
#define SM_TOTAL (2 * STAGE_BYTES)

#define SW(row, byte) (((row) * 128) + ((byte) ^ (((row) & 7) << 4)))

#define CP_ASYNC16(dst, src) \
    asm volatile("cp.async.cg.shared.global [%0], [%1], 16;" :: "r"(dst), "l"(src))
#define CP_COMMIT asm volatile("cp.async.commit_group;" ::: "memory")
#define CP_WAIT0  asm volatile("cp.async.wait_group 0;" ::: "memory")

__device__ __forceinline__ void mma_f16(float c[4], uint32_t a0, uint32_t a1,
                                        uint32_t a2, uint32_t a3,
                                        uint32_t b0, uint32_t b1) {
    asm volatile(
        "mma.sync.aligned.m16n8k16.row.col.f32.f16.f16.f32 "
        "{%0,%1,%2,%3}, {%4,%5,%6,%7}, {%8,%9}, {%0,%1,%2,%3};"
        : "+f"(c[0]), "+f"(c[1]), "+f"(c[2]), "+f"(c[3])
        : "r"(a0), "r"(a1), "r"(a2), "r"(a3), "r"(b0), "r"(b1));
}
#define LDSM_X4(r, a) \
    asm volatile("ldmatrix.sync.aligned.m8n8.x4.shared.b16 {%0,%1,%2,%3}, [%4];" \
        : "=r"((r)[0]), "=r"((r)[1]), "=r"((r)[2]), "=r"((r)[3]) : "r"(a))
#define LDSM_X4_T(r, a) \
    asm volatile("ldmatrix.sync.aligned.m8n8.x4.trans.shared.b16 {%0,%1,%2,%3}, [%4];" \
        : "=r"((r)[0]), "=r"((r)[1]), "=r"((r)[2]), "=r"((r)[3]) : "r"(a))

__device__ __forceinline__ uint32_t smem_to_u32(const void* p) {
    uint32_t a;
    asm("{ .reg .u64 t; cvta.to.shared.u64 t, %1; cvt.u32.u64 %0, t; }" : "=r"(a) : "l"(p));
    return a;
}
__device__ __forceinline__ float ex2(float x) {
    float r; asm("ex2.approx.ftz.f32 %0, %1;" : "=f"(r) : "f"(x)); return r;
}
__device__ __forceinline__ uint32_t packf16(float lo, float hi) {
    uint32_t r; asm("cvt.rn.f16x2.f32 %0, %1, %2;" : "=r"(r) : "f"(hi), "f"(lo)); return r;
}
__device__ __forceinline__ uint32_t h2ex2(uint32_t x) {
    uint32_t r; asm("ex2.approx.f16x2 %0, %1;" : "=r"(r) : "r"(x)); return r;
}
__device__ __forceinline__ uint32_t hmax2(uint32_t a, uint32_t b) {
    uint32_t r; asm("max.f16x2 %0, %1, %2;" : "=r"(r) : "r"(a), "r"(b)); return r;
}
// split (a,b) into packed fp16 hi pair + fp16 lo pair (22-bit effective)
__device__ __forceinline__ void split_pack_f16(float a, float b, uint32_t& hi, uint32_t& lo) {
    __half ha = __float2half_rn(a);
    __half hb = __float2half_rn(b);
    __half la = __float2half_rn(a - __half2float(ha));
    __half lb = __float2half_rn(b - __half2float(hb));
    hi = ((uint32_t)__half_as_ushort(hb) << 16) | (uint32_t)__half_as_ushort(ha);
    lo = ((uint32_t)__half_as_ushort(lb) << 16) | (uint32_t)__half_as_ushort(la);
}

// ---------------- preprocessing ----------------
__global__ void prep_kernel(const float* __restrict__ Q, const float* __restrict__ K,
                            const float* __restrict__ V, const float* __restrict__ tau,
                            const float* __restrict__ delta, int B, int L, int H)
{
    const int idx = blockIdx.x * blockDim.x + threadIdx.x;
    const int total = B * L * H * 16;
    if (idx < B * L) g_delta[idx] = delta[idx] * LOG2E_SCALE;
    if (idx >= total) return;
    const int e4 = (idx & 15) << 2;
    int t = idx >> 4;
    const int h = t % H; t /= H;
    const int l = t % L;
    const int b = t / L;

    const size_t in_ofs  = ((size_t)((b * L + l) * H + h)) * 64 + e4;
    const size_t out_ofs = ((size_t)((b * H + h) * L + l)) * 64 + e4;

    const float qs = tau[b] * LOG2E_SCALE;

    const float4 q = *(const float4*)(Q + in_ofs);
    *(uint2*)(g_Qh + out_ofs) =
        make_uint2(packf16(q.x * qs, q.y * qs), packf16(q.z * qs, q.w * qs));

    const float4 k = *(const float4*)(K + in_ofs);
    uint32_t h0, l0, h1, l1;
    split_pack_f16(k.x, k.y, h0, l0);
    split_pack_f16(k.z, k.w, h1, l1);
    *(uint2*)(g_Kh + out_ofs) = make_uint2(h0, h1);
    *(uint2*)(g_Kl + out_ofs) = make_uint2(l0, l1);

    const float4 v = *(const float4*)(V + in_ofs);
    *(uint2*)(g_Vh + out_ofs) = make_uint2(packf16(v.x, v.y), packf16(v.z, v.w));
}

// ---------------- stage one KV tile via cp.async ----------------
__device__ __forceinline__ void stage_tile(uint32_t sb,
                                           const __half* kh, const __half* kl,
                                           const __half* vh, const float* dl, int tid)
{
#pragma unroll
    for (int i = 0; i < 4; ++i) {
        const int c = tid + NTHREADS * i;
        const int r = c >> 3, s8 = (c & 7) << 3;
        const uint32_t d = SW(r, s8 * 2);
        const size_t go = (size_t)r * 64 + s8;
        CP_ASYNC16(sb + O_KH + d, kh + go);
        CP_ASYNC16(sb + O_KL + d, kl + go);
        CP_ASYNC16(sb + O_VH + d, vh + go);
    }
    if (tid < 16) CP_ASYNC16(sb + O_BETA + tid * 16, dl + tid * 4);
}

__global__ __launch_bounds__(NTHREADS, 3)
void dsattn8_kernel(float* __restrict__ Out, int B, int L, int H)
{
    extern __shared__ char smem[];
    const uint32_t smem_u32 = smem_to_u32(smem);

    const int tid  = threadIdx.x;
    const int wid  = tid >> 5;
    const int lane = tid & 31;
    const int g    = lane >> 2;
    const int t    = lane & 3;

    const uint32_t kb_row = (uint32_t)((lane & 7) | ((lane & 16) >> 1));
    const uint32_t kb_byt = (uint32_t)((lane & 8) << 1);
    const uint32_t vb_row = (uint32_t)(lane & 15);
    const uint32_t vb_byt = (uint32_t)((lane & 16) ? 16 : 0);

    const int qt = (int)(gridDim.x - 1u) - (int)blockIdx.x;  // heavy CTAs first
    const int bh = blockIdx.y;
    const int b  = bh / H;
    const int h  = bh % H;
    const int q0 = qt * BM;

    const size_t hb = (size_t)bh * L * 64;
    const int r0g = q0 + 16 * wid + g;
    const int r1g = r0g + 8;

    const __half* khp = g_Kh + hb;
    const __half* klp = g_Kl + hb;
    const __half* vhp = g_Vh + hb;
    const float*  dlp = g_delta + (size_t)b * L;

    stage_tile(smem_u32, khp, klp, vhp, dlp, tid);
    CP_COMMIT;

    // ---- Q A-fragments (single fp16, already scaled) ----
    uint32_t Qf[4][4];
    {
        const __half* q0p = g_Qh + hb + (size_t)r0g * 64;
        const __half* q1p = g_Qh + hb + (size_t)r1g * 64;
#pragma unroll
        for (int kb = 0; kb < 4; ++kb) {
#pragma unroll
            for (int h2 = 0; h2 < 2; ++h2) {
                const int col = 16 * kb + 2 * t + 8 * h2;
                Qf[kb][2 * h2 + 0] = *(const uint32_t*)(q0p + col);
                Qf[kb][2 * h2 + 1] = *(const uint32_t*)(q1p + col);
            }
        }
    }

    float m0 = -1e30f, m1 = -1e30f;
    float lacc[4] = {0.f, 0.f, 0.f, 0.f};
    float O[8][4];
#pragma unroll
    for (int j = 0; j < 8; ++j)
#pragma unroll
        for (int i = 0; i < 4; ++i) O[j][i] = 0.0f;

    const uint32_t ONES = 0x3C003C00u;  // fp16 (1.0, 1.0)

    const int nkv = qt + 1;
    for (int nt = 0; nt < nkv; ++nt) {
        const int cur = nt & 1;
        const uint32_t bufc = smem_u32 + (uint32_t)cur * STAGE_BYTES;

        CP_WAIT0;
        __syncthreads();

        if (nt + 1 < nkv) {
            const int n1 = (nt + 1) * BN;
            stage_tile(smem_u32 + (uint32_t)(cur ^ 1) * STAGE_BYTES,
                       khp + (size_t)n1 * 64, klp + (size_t)n1 * 64,
                       vhp + (size_t)n1 * 64, dlp + n1, tid);
            CP_COMMIT;
        }

        // ---- S = Q.K^T : 2 fp16 terms (Qh.Kh + Qh.Kl) ----
        float S[8][4];
#pragma unroll
        for (int j = 0; j < 8; ++j)
#pragma unroll
            for (int i = 0; i < 4; ++i) S[j][i] = 0.0f;

#pragma unroll
        for (int kb = 0; kb < 4; ++kb) {
#pragma unroll
            for (int njp = 0; njp < 4; ++njp) {
                uint32_t kh[4], kl[4];
                const uint32_t ofs = SW(16u * njp + kb_row, 32u * kb + kb_byt);
                LDSM_X4(kh, bufc + O_KH + ofs);
                LDSM_X4(kl, bufc + O_KL + ofs);
                mma_f16(S[2 * njp],     Qf[kb][0], Qf[kb][1], Qf[kb][2], Qf[kb][3], kh[0], kh[1]);
                mma_f16(S[2 * njp],     Qf[kb][0], Qf[kb][1], Qf[kb][2], Qf[kb][3], kl[0], kl[1]);
                mma_f16(S[2 * njp + 1], Qf[kb][0], Qf[kb][1], Qf[kb][2], Qf[kb][3], kh[2], kh[3]);
                mma_f16(S[2 * njp + 1], Qf[kb][0], Qf[kb][1], Qf[kb][2], Qf[kb][3], kl[2], kl[3]);
            }
        }

        // ---- bias (prescaled) + causal mask ----
        const float* beta_c = (const float*)(smem + cur * STAGE_BYTES + O_BETA);
#pragma unroll
        for (int nj = 0; nj < 8; ++nj) {
            const float2 bv = *(const float2*)(beta_c + 8 * nj + 2 * t);
            S[nj][0] += bv.x; S[nj][1] += bv.y;
            S[nj][2] += bv.x; S[nj][3] += bv.y;
        }
        if (nt == qt) {
            const int c0b = nt * BN + 2 * t;
#pragma unroll
            for (int nj = 0; nj < 8; ++nj) {
                const int c = c0b + 8 * nj;
                if (c     > r0g) S[nj][0] = -30000.0f;
                if (c + 1 > r0g) S[nj][1] = -30000.0f;
                if (c     > r1g) S[nj][2] = -30000.0f;
                if (c + 1 > r1g) S[nj][3] = -30000.0f;
            }
        }

        // ---- packed row max ----
        float nm0 = m0, nm1 = m1;
#pragma unroll
        for (int nj = 0; nj < 8; ++nj) {
            nm0 = fmaxf(nm0, fmaxf(S[nj][0], S[nj][1]));
            nm1 = fmaxf(nm1, fmaxf(S[nj][2], S[nj][3]));
        }
        uint32_t pm = packf16(nm0, nm1);
        pm = hmax2(pm, __shfl_xor_sync(0xffffffffu, pm, 1));
        pm = hmax2(pm, __shfl_xor_sync(0xffffffffu, pm, 2));
        const __half2 mh = *reinterpret_cast<const __half2*>(&pm);
        nm0 = __low2float(mh);
        nm1 = __high2float(mh);

        // ---- conditional accumulator rescale ----
        if (!__all_sync(0xffffffffu, (nm0 == m0) & (nm1 == m1))) {
            const float corr0 = ex2(m0 - nm0);
            const float corr1 = ex2(m1 - nm1);
#pragma unroll
            for (int nj = 0; nj < 8; ++nj) {
                O[nj][0] *= corr0; O[nj][1] *= corr0;
                O[nj][2] *= corr1; O[nj][3] *= corr1;
            }
            lacc[0] *= corr0; lacc[1] *= corr0;
            lacc[2] *= corr1; lacc[3] *= corr1;
        }
        m0 = nm0; m1 = nm1;

        // ---- P = exp2(S - m) in fp16x2 (A-fragment layout) ----
        uint32_t Ph[8][2];
#pragma unroll
        for (int nj = 0; nj < 8; ++nj) {
            Ph[nj][0] = h2ex2(packf16(S[nj][0] - nm0, S[nj][1] - nm0));
            Ph[nj][1] = h2ex2(packf16(S[nj][2] - nm1, S[nj][3] - nm1));
        }

        // ---- O += P.V and l += P.1 (fp16, single term) ----
#pragma unroll
        for (int jk = 0; jk < 4; ++jk) {
            const uint32_t a0 = Ph[2 * jk][0], a1 = Ph[2 * jk][1];
            const uint32_t a2 = Ph[2 * jk + 1][0], a3 = Ph[2 * jk + 1][1];
            mma_f16(lacc, a0, a1, a2, a3, ONES, ONES);
#pragma unroll
            for (int njp = 0; njp < 4; ++njp) {
                uint32_t vh[4];
                const uint32_t ofs = SW(16u * jk + vb_row, 32u * njp + vb_byt);
                LDSM_X4_T(vh, bufc + O_VH + ofs);
                mma_f16(O[2 * njp],     a0, a1, a2, a3, vh[0], vh[1]);
                mma_f16(O[2 * njp + 1], a0, a1, a2, a3, vh[2], vh[3]);
            }
        }
        // no end-of-loop sync: next iteration's top sync guards buffer reuse
    }

    // ---- epilogue ----
    const float inv0 = 1.0f / lacc[0];
    const float inv1 = 1.0f / lacc[2];
    float* o0p = Out + ((size_t)((b * L + r0g) * H + h)) * 64;
    float* o1p = Out + ((size_t)((b * L + r1g) * H + h)) * 64;
#pragma unroll
    for (int nj = 0; nj < 8; ++nj) {
        const int d = 8 * nj + 2 * t;
        *(float2*)(o0p + d) = make_float2(O[nj][0] * inv0, O[nj][1] * inv0);
        *(float2*)(o1p + d) = make_float2(O[nj][2] * inv1, O[nj][3] * inv1);
    }
}

extern "C" void kernel_launch(void* const* d_in, const int* in_sizes, int n_in,
                              void* d_out, int out_size)
{
    const float* Q     = (const float*)d_in[0];
    const float* K     = (const float*)d_in[1];
    const float* V     = (const float*)d_in[2];
    const float* tau   = (const float*)d_in[3];
    const float* delta = (const float*)d_in[4];
    float* O = (float*)d_out;

    const int B = in_sizes[3];
    const int L = in_sizes[4] / B;
    const int H = in_sizes[0] / (B * L * 64);

    const int total4 = B * L * H * 16;
    prep_kernel<<<(total4 + 255) / 256, 256>>>(Q, K, V, tau, delta, B, L, H);

    cudaFuncSetAttribute(dsattn8_kernel,
                         cudaFuncAttributeMaxDynamicSharedMemorySize, SM_TOTAL);
    dim3 grid(L / BM, B * H);
    dsattn8_kernel<<<grid, NTHREADS, SM_TOTAL>>>(O, B, L, H);
}

// round 14
// speedup vs baseline: 1.6675x; 1.2875x over previous
#include <cuda_runtime.h>
#include <cuda_bf16.h>
#include <cuda_fp16.h>
#include <cstdint>
#include <cstddef>

// DSAttention: preprocessed fp16 operands. QK = single-term fp16 mma.sync,
// PV = single-term fp16 (minimum HMMA count: 68/warp-step).
// cp.async double-buffer, single sync/step, packed f16x2 max, cond rescale.

#define LOG2E_SCALE 0.18033688011112042f   // (1/8)*log2(e)
#define PMAX (4 * 8 * 2048 * 64)           // B*H*L*E
#define DMAX (4 * 2048)                    // B*L

__device__ __half g_Qh[PMAX];
__device__ __half g_Kh[PMAX];
__device__ __half g_Vh[PMAX];
__device__ float  g_delta[DMAX];

#define NTHREADS 128
#define BM 64
#define BN 64

#define O_KH 0
#define O_VH 8192
#define O_BETA 16384
#define STAGE_BYTES 16640
#define SM_TOTAL (2 * STAGE_BYTES)

#define SW(row, byte) (((row) * 128) + ((byte) ^ (((row) & 7) << 4)))

#define CP_ASYNC16(dst, src) \
    asm volatile("cp.async.cg.shared.global [%0], [%1], 16;" :: "r"(dst), "l"(src))
#define CP_COMMIT asm volatile("cp.async.commit_group;" ::: "memory")
#define CP_WAIT0  asm volatile("cp.async.wait_group 0;" ::: "memory")

__device__ __forceinline__ void mma_f16(float c[4], uint32_t a0, uint32_t a1,
                                        uint32_t a2, uint32_t a3,
                                        uint32_t b0, uint32_t b1) {
    asm volatile(
        "mma.sync.aligned.m16n8k16.row.col.f32.f16.f16.f32 "
        "{%0,%1,%2,%3}, {%4,%5,%6,%7}, {%8,%9}, {%0,%1,%2,%3};"
        : "+f"(c[0]), "+f"(c[1]), "+f"(c[2]), "+f"(c[3])
        : "r"(a0), "r"(a1), "r"(a2), "r"(a3), "r"(b0), "r"(b1));
}
#define LDSM_X4(r, a) \
    asm volatile("ldmatrix.sync.aligned.m8n8.x4.shared.b16 {%0,%1,%2,%3}, [%4];" \
        : "=r"((r)[0]), "=r"((r)[1]), "=r"((r)[2]), "=r"((r)[3]) : "r"(a))
#define LDSM_X4_T(r, a) \
    asm volatile("ldmatrix.sync.aligned.m8n8.x4.trans.shared.b16 {%0,%1,%2,%3}, [%4];" \
        : "=r"((r)[0]), "=r"((r)[1]), "=r"((r)[2]), "=r"((r)[3]) : "r"(a))

__device__ __forceinline__ uint32_t smem_to_u32(const void* p) {
    uint32_t a;
    asm("{ .reg .u64 t; cvta.to.shared.u64 t, %1; cvt.u32.u64 %0, t; }" : "=r"(a) : "l"(p));
    return a;
}
__device__ __forceinline__ float ex2(float x) {
    float r; asm("ex2.approx.ftz.f32 %0, %1;" : "=f"(r) : "f"(x)); return r;
}
__device__ __forceinline__ uint32_t packf16(float lo, float hi) {
    uint32_t r; asm("cvt.rn.f16x2.f32 %0, %1, %2;" : "=r"(r) : "f"(hi), "f"(lo)); return r;
}
__device__ __forceinline__ uint32_t h2ex2(uint32_t x) {
    uint32_t r; asm("ex2.approx.f16x2 %0, %1;" : "=r"(r) : "r"(x)); return r;
}
__device__ __forceinline__ uint32_t hmax2(uint32_t a, uint32_t b) {
    uint32_t r; asm("max.f16x2 %0, %1, %2;" : "=r"(r) : "r"(a), "r"(b)); return r;
}

// ---------------- preprocessing: fp32 [b,l,h,e] -> fp16 [b,h,l,e] ----------------
__global__ void prep_kernel(const float* __restrict__ Q, const float* __restrict__ K,
                            const float* __restrict__ V, const float* __restrict__ tau,
                            const float* __restrict__ delta, int B, int L, int H)
{
    const int idx = blockIdx.x * blockDim.x + threadIdx.x;
    const int total = B * L * H * 16;
    if (idx < B * L) g_delta[idx] = delta[idx] * LOG2E_SCALE;
    if (idx >= total) return;
    const int e4 = (idx & 15) << 2;
    int t = idx >> 4;
    const int h = t % H; t /= H;
    const int l = t % L;
    const int b = t / L;

    const size_t in_ofs  = ((size_t)((b * L + l) * H + h)) * 64 + e4;
    const size_t out_ofs = ((size_t)((b * H + h) * L + l)) * 64 + e4;

    const float qs = tau[b] * LOG2E_SCALE;

    const float4 q = *(const float4*)(Q + in_ofs);
    *(uint2*)(g_Qh + out_ofs) =
        make_uint2(packf16(q.x * qs, q.y * qs), packf16(q.z * qs, q.w * qs));

    const float4 k = *(const float4*)(K + in_ofs);
    *(uint2*)(g_Kh + out_ofs) = make_uint2(packf16(k.x, k.y), packf16(k.z, k.w));

    const float4 v = *(const float4*)(V + in_ofs);
    *(uint2*)(g_Vh + out_ofs) = make_uint2(packf16(v.x, v.y), packf16(v.z, v.w));
}

// ---------------- stage one KV tile via cp.async (2 tiles + beta) ----------------
__device__ __forceinline__ void stage_tile(uint32_t sb,
                                           const __half* kh, const __half* vh,
                                           const float* dl, int tid)
{
#pragma unroll
    for (int i = 0; i < 4; ++i) {
        const int c = tid + NTHREADS * i;
        const int r = c >> 3, s8 = (c & 7) << 3;
        const uint32_t d = SW(r, s8 * 2);
        const size_t go = (size_t)r * 64 + s8;
        CP_ASYNC16(sb + O_KH + d, kh + go);
        CP_ASYNC16(sb + O_VH + d, vh + go);
    }
    if (tid < 16) CP_ASYNC16(sb + O_BETA + tid * 16, dl + tid * 4);
}

__global__ __launch_bounds__(NTHREADS, 3)
void dsattn9_kernel(float* __restrict__ Out, int B, int L, int H)
{
    extern __shared__ char smem[];
    const uint32_t smem_u32 = smem_to_u32(smem);

    const int tid  = threadIdx.x;
    const int wid  = tid >> 5;
    const int lane = tid & 31;
    const int g    = lane >> 2;
    const int t    = lane & 3;

    const uint32_t kb_row = (uint32_t)((lane & 7) | ((lane & 16) >> 1));
    const uint32_t kb_byt = (uint32_t)((lane & 8) << 1);
    const uint32_t vb_row = (uint32_t)(lane & 15);
    const uint32_t vb_byt = (uint32_t)((lane & 16) ? 16 : 0);

    const int qt = (int)(gridDim.x - 1u) - (int)blockIdx.x;  // heavy CTAs first
    const int bh = blockIdx.y;
    const int b  = bh / H;
    const int h  = bh % H;
    const int q0 = qt * BM;

    const size_t hb = (size_t)bh * L * 64;
    const int r0g = q0 + 16 * wid + g;
    const int r1g = r0g + 8;

    const __half* khp = g_Kh + hb;
    const __half* vhp = g_Vh + hb;
    const float*  dlp = g_delta + (size_t)b * L;

    stage_tile(smem_u32, khp, vhp, dlp, tid);
    CP_COMMIT;

    // ---- Q A-fragments (single fp16, already scaled) ----
    uint32_t Qf[4][4];
    {
        const __half* q0p = g_Qh + hb + (size_t)r0g * 64;
        const __half* q1p = g_Qh + hb + (size_t)r1g * 64;
#pragma unroll
        for (int kb = 0; kb < 4; ++kb) {
#pragma unroll
            for (int h2 = 0; h2 < 2; ++h2) {
                const int col = 16 * kb + 2 * t + 8 * h2;
                Qf[kb][2 * h2 + 0] = *(const uint32_t*)(q0p + col);
                Qf[kb][2 * h2 + 1] = *(const uint32_t*)(q1p + col);
            }
        }
    }

    float m0 = -1e30f, m1 = -1e30f;
    float lacc[4] = {0.f, 0.f, 0.f, 0.f};
    float O[8][4];
#pragma unroll
    for (int j = 0; j < 8; ++j)
#pragma unroll
        for (int i = 0; i < 4; ++i) O[j][i] = 0.0f;

    const uint32_t ONES = 0x3C003C00u;  // fp16 (1.0, 1.0)

    const int nkv = qt + 1;
    for (int nt = 0; nt < nkv; ++nt) {
        const int cur = nt & 1;
        const uint32_t bufc = smem_u32 + (uint32_t)cur * STAGE_BYTES;

        CP_WAIT0;
        __syncthreads();

        if (nt + 1 < nkv) {
            const int n1 = (nt + 1) * BN;
            stage_tile(smem_u32 + (uint32_t)(cur ^ 1) * STAGE_BYTES,
                       khp + (size_t)n1 * 64, vhp + (size_t)n1 * 64, dlp + n1, tid);
            CP_COMMIT;
        }

        // ---- S = Q.K^T : single fp16 term ----
        float S[8][4];
#pragma unroll
        for (int j = 0; j < 8; ++j)
#pragma unroll
            for (int i = 0; i < 4; ++i) S[j][i] = 0.0f;

#pragma unroll
        for (int kb = 0; kb < 4; ++kb) {
#pragma unroll
            for (int njp = 0; njp < 4; ++njp) {
                uint32_t kh[4];
                const uint32_t ofs = SW(16u * njp + kb_row, 32u * kb + kb_byt);
                LDSM_X4(kh, bufc + O_KH + ofs);
                mma_f16(S[2 * njp],     Qf[kb][0], Qf[kb][1], Qf[kb][2], Qf[kb][3], kh[0], kh[1]);
                mma_f16(S[2 * njp + 1], Qf[kb][0], Qf[kb][1], Qf[kb][2], Qf[kb][3], kh[2], kh[3]);
            }
        }

        // ---- bias (prescaled) + causal mask ----
        const float* beta_c = (const float*)(smem + cur * STAGE_BYTES + O_BETA);
#pragma unroll
        for (int nj = 0; nj < 8; ++nj) {
            const float2 bv = *(const float2*)(beta_c + 8 * nj + 2 * t);
            S[nj][0] += bv.x; S[nj][1] += bv.y;
            S[nj][2] += bv.x; S[nj][3] += bv.y;
        }
        if (nt == qt) {
            const int c0b = nt * BN + 2 * t;
#pragma unroll
            for (int nj = 0; nj < 8; ++nj) {
                const int c = c0b + 8 * nj;
                if (c     > r0g) S[nj][0] = -30000.0f;
                if (c + 1 > r0g) S[nj][1] = -30000.0f;
                if (c     > r1g) S[nj][2] = -30000.0f;
                if (c + 1 > r1g) S[nj][3] = -30000.0f;
            }
        }

        // ---- packed row max ----
        float nm0 = m0, nm1 = m1;
#pragma unroll
        for (int nj = 0; nj < 8; ++nj) {
            nm0 = fmaxf(nm0, fmaxf(S[nj][0], S[nj][1]));
            nm1 = fmaxf(nm1, fmaxf(S[nj][2], S[nj][3]));
        }
        uint32_t pm = packf16(nm0, nm1);
        pm = hmax2(pm, __shfl_xor_sync(0xffffffffu, pm, 1));
        pm = hmax2(pm, __shfl_xor_sync(0xffffffffu, pm, 2));
        const __half2 mh = *reinterpret_cast<const __half2*>(&pm);
        nm0 = __low2float(mh);
        nm1 = __high2float(mh);

        // ---- conditional accumulator rescale ----
        if (!__all_sync(0xffffffffu, (nm0 == m0) & (nm1 == m1))) {
            const float corr0 = ex2(m0 - nm0);
            const float corr1 = ex2(m1 - nm1);
#pragma unroll
            for (int nj = 0; nj < 8; ++nj) {
                O[nj][0] *= corr0; O[nj][1] *= corr0;
                O[nj][2] *= corr1; O[nj][3] *= corr1;
            }
            lacc[0] *= corr0; lacc[1] *= corr0;
            lacc[2] *= corr1; lacc[3] *= corr1;
        }
        m0 = nm0; m1 = nm1;

        // ---- P = exp2(S - m) in fp16x2 (A-fragment layout) ----
        uint32_t Ph[8][2];
#pragma unroll
        for (int nj = 0; nj < 8; ++nj) {
            Ph[nj][0] = h2ex2(packf16(S[nj][0] - nm0, S[nj][1] - nm0));
            Ph[nj][1] = h2ex2(packf16(S[nj][2] - nm1, S[nj][3] - nm1));
        }

        // ---- O += P.V and l += P.1 (fp16, single term) ----
#pragma unroll
        for (int jk = 0; jk < 4; ++jk) {
            const uint32_t a0 = Ph[2 * jk][0], a1 = Ph[2 * jk][1];
            const uint32_t a2 = Ph[2 * jk + 1][0], a3 = Ph[2 * jk + 1][1];
            mma_f16(lacc, a0, a1, a2, a3, ONES, ONES);
#pragma unroll
            for (int njp = 0; njp < 4; ++njp) {
                uint32_t vh[4];
                const uint32_t ofs = SW(16u * jk + vb_row, 32u * njp + vb_byt);
                LDSM_X4_T(vh, bufc + O_VH + ofs);
                mma_f16(O[2 * njp],     a0, a1, a2, a3, vh[0], vh[1]);
                mma_f16(O[2 * njp + 1], a0, a1, a2, a3, vh[2], vh[3]);
            }
        }
        // no end-of-loop sync: next iteration's top sync guards buffer reuse
    }

    // ---- epilogue ----
    const float inv0 = 1.0f / lacc[0];
    const float inv1 = 1.0f / lacc[2];
    float* o0p = Out + ((size_t)((b * L + r0g) * H + h)) * 64;
    float* o1p = Out + ((size_t)((b * L + r1g) * H + h)) * 64;
#pragma unroll
    for (int nj = 0; nj < 8; ++nj) {
        const int d = 8 * nj + 2 * t;
        *(float2*)(o0p + d) = make_float2(O[nj][0] * inv0, O[nj][1] * inv0);
        *(float2*)(o1p + d) = make_float2(O[nj][2] * inv1, O[nj][3] * inv1);
    }
}

extern "C" void kernel_launch(void* const* d_in, const int* in_sizes, int n_in,
                              void* d_out, int out_size)
{
    const float* Q     = (const float*)d_in[0];
    const float* K     = (const float*)d_in[1];
    const float* V     = (const float*)d_in[2];
    const float* tau   = (const float*)d_in[3];
    const float* delta = (const float*)d_in[4];
    float* O = (float*)d_out;

    const int B = in_sizes[3];
    const int L = in_sizes[4] / B;
    const int H = in_sizes[0] / (B * L * 64);

    const int total4 = B * L * H * 16;
    prep_kernel<<<(total4 + 255) / 256, 256>>>(Q, K, V, tau, delta, B, L, H);

    cudaFuncSetAttribute(dsattn9_kernel,
                         cudaFuncAttributeMaxDynamicSharedMemorySize, SM_TOTAL);
    dim3 grid(L / BM, B * H);
    dsattn9_kernel<<<grid, NTHREADS, SM_TOTAL>>>(O, B, L, H);
}